// round 4
// baseline (speedup 1.0000x reference)
#include <cuda_runtime.h>
#include <cuda_bf16.h>
#include <cstdint>

// custom_loss_57956288692862
// x: [16384,1024] fp32 -> 4096 groups of 4 rows: q=4b+0, a=4b+1, dead=4b+2, c=4b+3
// target: [2,4096] int32
// out fp32[4097]: out[0]=mean loss, out[1+b]=eq flag
//
// TMA (cp.async.bulk) + mbarrier pipeline: the copy engine streams group tiles
// into a 3-deep smem ring independently of the warps, so reduction tails no
// longer idle the memory pipe (R3's convoy problem). Cross-warp combine and the
// exp/log epilogue are deferred to one batched pass at the end of the CTA.

#define NB      4096
#define D       1024
#define THREADS 256
#define GRID    296            // 2 CTAs/SM on 148 SMs, single wave
#define DEPTH   3              // smem ring depth (3 x 12KB)
#define MAXG    14             // ceil(4096/296)
#define SLOT_BYTES 12288       // q(4KB) + a(4KB) + c(4KB)

__global__ void zero_out0_kernel(float* out) {
    if (threadIdx.x == 0) out[0] = 0.0f;
}

__device__ __forceinline__ uint32_t smem_u32(const void* p) {
    return (uint32_t)__cvta_generic_to_shared(p);
}

__device__ __forceinline__ void mbar_init(uint32_t bar, uint32_t count) {
    asm volatile("mbarrier.init.shared.b64 [%0], %1;" :: "r"(bar), "r"(count) : "memory");
}

__device__ __forceinline__ void mbar_arrive(uint32_t bar) {
    asm volatile("mbarrier.arrive.shared.b64 _, [%0];" :: "r"(bar) : "memory");
}

__device__ __forceinline__ void mbar_expect_tx(uint32_t bar, uint32_t bytes) {
    asm volatile("mbarrier.arrive.expect_tx.shared.b64 _, [%0], %1;"
                 :: "r"(bar), "r"(bytes) : "memory");
}

__device__ __forceinline__ void mbar_wait(uint32_t bar, uint32_t parity) {
    uint32_t done;
    do {
        asm volatile(
            "{\n\t"
            ".reg .pred p;\n\t"
            "mbarrier.try_wait.parity.shared.b64 p, [%1], %2;\n\t"
            "selp.b32 %0, 1, 0, p;\n\t"
            "}"
            : "=r"(done) : "r"(bar), "r"(parity) : "memory");
    } while (!done);
}

__device__ __forceinline__ void bulk_copy(uint32_t dst_smem, const void* src,
                                          uint32_t bytes, uint32_t bar) {
    asm volatile(
        "cp.async.bulk.shared::cta.global.mbarrier::complete_tx::bytes "
        "[%0], [%1], %2, [%3];"
        :: "r"(dst_smem), "l"(src), "r"(bytes), "r"(bar) : "memory");
}

__global__ __launch_bounds__(THREADS)
void loss_kernel(const float* __restrict__ x,
                 const int* __restrict__ target,
                 float* __restrict__ out,
                 int out_size) {
    __shared__ __align__(128) unsigned char buf[DEPTH][SLOT_BYTES];
    __shared__ uint64_t mb_full[DEPTH];
    __shared__ uint64_t mb_empty[DEPTH];
    __shared__ float scratch[MAXG][8][6];   // per-group, per-warp partials

    const int t   = threadIdx.x;
    const int wid = t >> 5;
    const int lid = t & 31;
    const int bid = blockIdx.x;

    // Number of groups this CTA owns: b = bid + it*GRID, b < NB
    const int n = (NB - 1 - bid) / GRID + 1;   // 13 or 14

    uint32_t full_a[DEPTH], empty_a[DEPTH];
    #pragma unroll
    for (int s = 0; s < DEPTH; s++) {
        full_a[s]  = smem_u32(&mb_full[s]);
        empty_a[s] = smem_u32(&mb_empty[s]);
    }

    if (t == 0) {
        #pragma unroll
        for (int s = 0; s < DEPTH; s++) {
            mbar_init(full_a[s], 1);        // one expect_tx arrive + tx bytes
            mbar_init(empty_a[s], THREADS); // every thread arrives after consume
        }
        asm volatile("fence.proxy.async.shared::cta;" ::: "memory");
    }
    __syncthreads();

    // Prologue: fill the ring
    if (t == 0) {
        #pragma unroll
        for (int s = 0; s < DEPTH; s++) {
            if (s < n) {
                const char* src = (const char*)x + ((size_t)(bid + s * GRID)) * (4 * D * 4);
                mbar_expect_tx(full_a[s], SLOT_BYTES);
                bulk_copy(smem_u32(&buf[s][0]),        src,          8192, full_a[s]); // q+a
                bulk_copy(smem_u32(&buf[s][0]) + 8192, src + 12288,  4096, full_a[s]); // c
            }
        }
    }

    for (int it = 0; it < n; it++) {
        const int s = it % DEPTH;
        const uint32_t ph = (uint32_t)((it / DEPTH) & 1);

        mbar_wait(full_a[s], ph);

        // Consume: 3 x LDS.128 per thread (conflict-free, lane-consecutive)
        const float4 q4 = *reinterpret_cast<const float4*>(&buf[s][t * 16]);
        const float4 a4 = *reinterpret_cast<const float4*>(&buf[s][4096 + t * 16]);
        const float4 c4 = *reinterpret_cast<const float4*>(&buf[s][8192 + t * 16]);

        float nq = q4.x * q4.x + q4.y * q4.y + q4.z * q4.z + q4.w * q4.w;
        float na = a4.x * a4.x + a4.y * a4.y + a4.z * a4.z + a4.w * a4.w;
        float nc = c4.x * c4.x + c4.y * c4.y + c4.z * c4.z + c4.w * c4.w;
        float qa = q4.x * a4.x + q4.y * a4.y + q4.z * a4.z + q4.w * a4.w;
        float ac = a4.x * c4.x + a4.y * c4.y + a4.z * c4.z + a4.w * c4.w;
        float qc = q4.x * c4.x + q4.y * c4.y + q4.z * c4.z + q4.w * c4.w;

        // Values consumed into registers -> slot reusable
        mbar_arrive(empty_a[s]);

        // Warp butterfly (6 independent chains)
        #pragma unroll
        for (int off = 16; off > 0; off >>= 1) {
            nq += __shfl_xor_sync(0xFFFFFFFFu, nq, off);
            na += __shfl_xor_sync(0xFFFFFFFFu, na, off);
            nc += __shfl_xor_sync(0xFFFFFFFFu, nc, off);
            qa += __shfl_xor_sync(0xFFFFFFFFu, qa, off);
            ac += __shfl_xor_sync(0xFFFFFFFFu, ac, off);
            qc += __shfl_xor_sync(0xFFFFFFFFu, qc, off);
        }
        if (lid == 0) {
            scratch[it][wid][0] = nq; scratch[it][wid][1] = na;
            scratch[it][wid][2] = nc; scratch[it][wid][3] = qa;
            scratch[it][wid][4] = ac; scratch[it][wid][5] = qc;
        }

        // Producer refill: needs this iteration's 256 arrivals on empty[s]
        if (t == 0 && it + DEPTH < n) {
            mbar_wait(empty_a[s], (uint32_t)((it / DEPTH) & 1));
            const char* src = (const char*)x + ((size_t)(bid + (it + DEPTH) * GRID)) * (4 * D * 4);
            mbar_expect_tx(full_a[s], SLOT_BYTES);
            bulk_copy(smem_u32(&buf[s][0]),        src,         8192, full_a[s]);
            bulk_copy(smem_u32(&buf[s][0]) + 8192, src + 12288, 4096, full_a[s]);
        }
    }
    __syncthreads();

    // Deferred finalization: one group per thread, fully parallel
    float locLoss = 0.0f;
    if (t < n) {
        float snq = 0.f, sna = 0.f, snc = 0.f, sqa = 0.f, sac = 0.f, sqc = 0.f;
        #pragma unroll
        for (int w = 0; w < 8; w++) {
            snq += scratch[t][w][0]; sna += scratch[t][w][1];
            snc += scratch[t][w][2]; sqa += scratch[t][w][3];
            sac += scratch[t][w][4]; sqc += scratch[t][w][5];
        }
        const int b = bid + t * GRID;

        float iq = 1.0f / fmaxf(sqrtf(snq), 1e-12f);
        float ia = 1.0f / fmaxf(sqrtf(sna), 1e-12f);
        float ic = 1.0f / fmaxf(sqrtf(snc), 1e-12f);

        float dqa = sqa * iq * ia;
        float dac = sac * ia * ic;
        float dqc = sqc * iq * ic;

        float t0 = (float)target[b];
        float t1 = (float)target[NB + b];

        float eqa = __expf(dqa);
        float eac = __expf(dac);
        float eqc = __expf(dqc);

        float up   = fmaxf((1.0f - t0) * eqa + (1.0f - t1) * eqc, 1e-8f);
        float down = fmaxf(t0 * eqa + t1 * eqc, 1e-8f);

        locLoss = __logf(up + eac) - __logf(down);

        int correct = (dqa > dqc) ? 1 : 0;
        float eq = (correct == (int)t0) ? 1.0f : 0.0f;
        if (1 + b < out_size) out[1 + b] = eq;
    }

    // Loss-bearing threads are 0..n-1 (n <= 14), all in warp 0
    if (wid == 0) {
        #pragma unroll
        for (int off = 16; off > 0; off >>= 1)
            locLoss += __shfl_xor_sync(0xFFFFFFFFu, locLoss, off);
        if (lid == 0) atomicAdd(&out[0], locLoss * (1.0f / (float)NB));
    }
}

extern "C" void kernel_launch(void* const* d_in, const int* in_sizes, int n_in,
                              void* d_out, int out_size) {
    const float* x      = (const float*)d_in[0];
    const int*   target = (const int*)d_in[1];
    float*       out    = (float*)d_out;

    zero_out0_kernel<<<1, 32>>>(out);
    loss_kernel<<<GRID, THREADS>>>(x, target, out, out_size);
}

// round 5
// speedup vs baseline: 1.4679x; 1.4679x over previous
#include <cuda_runtime.h>
#include <cuda_bf16.h>
#include <cstdint>

// custom_loss_57956288692862
// x: [16384,1024] fp32 -> 4096 groups of 4 rows: q=4b+0, a=4b+1, dead=4b+2, c=4b+3
// target: [2,4096] int32
// out fp32[4097]: out[0]=mean loss, out[1+b]=eq flag
//
// Single kernel. 1024 CTAs x 128 thr (launch_bounds(128,8) -> ~26 warps/SM, one
// wave). One warp per group: targets prefetched up front, 2 stages of 12
// front-batched LDG.128, butterfly reduce, lane-0 epilogue. Loss mean via
// per-CTA partials + last-CTA reduction (ticket counter reset each launch for
// graph-replay determinism) -> no second kernel, no out[0] pre-zero.

#define NB      4096
#define D       1024
#define THREADS 128
#define GRID    1024           // 4096 groups / (4 warps per CTA)

__device__ float        g_partials[GRID];
__device__ unsigned int g_count;    // zero-init; last CTA resets it every launch

__global__ __launch_bounds__(THREADS, 8)
void loss_kernel(const float* __restrict__ x,
                 const int* __restrict__ target,
                 float* __restrict__ out,
                 int out_size) {
    const int t   = threadIdx.x;
    const int wid = t >> 5;
    const int lid = t & 31;
    const int b   = blockIdx.x * 4 + wid;    // group id, < 4096

    // ---- Prefetch targets early (latency overlapped with row loads) ----
    int t0i = 0, t1i = 0;
    if (lid == 0) {
        t0i = __ldg(target + b);
        t1i = __ldg(target + NB + b);
    }

    // Group base: 4 rows * 1024 floats = 1024 float4; row stride = 256 float4.
    const float4* __restrict__ g =
        reinterpret_cast<const float4*>(x + (size_t)b * (4 * D));

    float nq = 0.f, na = 0.f, nc = 0.f, qa = 0.f, ac = 0.f, qc = 0.f;

    #pragma unroll
    for (int stage = 0; stage < 2; stage++) {
        float4 q4[4], a4[4], c4[4];
        const int j0 = stage * 4;
        #pragma unroll
        for (int j = 0; j < 4; j++) {
            const int idx = lid + 32 * (j0 + j);
            q4[j] = g[idx];          // row 4b+0
            a4[j] = g[256 + idx];    // row 4b+1
            c4[j] = g[768 + idx];    // row 4b+3
        }
        #pragma unroll
        for (int j = 0; j < 4; j++) {
            nq = fmaf(q4[j].x, q4[j].x, nq); nq = fmaf(q4[j].y, q4[j].y, nq);
            nq = fmaf(q4[j].z, q4[j].z, nq); nq = fmaf(q4[j].w, q4[j].w, nq);
            na = fmaf(a4[j].x, a4[j].x, na); na = fmaf(a4[j].y, a4[j].y, na);
            na = fmaf(a4[j].z, a4[j].z, na); na = fmaf(a4[j].w, a4[j].w, na);
            nc = fmaf(c4[j].x, c4[j].x, nc); nc = fmaf(c4[j].y, c4[j].y, nc);
            nc = fmaf(c4[j].z, c4[j].z, nc); nc = fmaf(c4[j].w, c4[j].w, nc);
            qa = fmaf(q4[j].x, a4[j].x, qa); qa = fmaf(q4[j].y, a4[j].y, qa);
            qa = fmaf(q4[j].z, a4[j].z, qa); qa = fmaf(q4[j].w, a4[j].w, qa);
            ac = fmaf(a4[j].x, c4[j].x, ac); ac = fmaf(a4[j].y, c4[j].y, ac);
            ac = fmaf(a4[j].z, c4[j].z, ac); ac = fmaf(a4[j].w, c4[j].w, ac);
            qc = fmaf(q4[j].x, c4[j].x, qc); qc = fmaf(q4[j].y, c4[j].y, qc);
            qc = fmaf(q4[j].z, c4[j].z, qc); qc = fmaf(q4[j].w, c4[j].w, qc);
        }
    }

    // Warp butterfly (6 chains, no smem)
    #pragma unroll
    for (int off = 16; off > 0; off >>= 1) {
        nq += __shfl_xor_sync(0xFFFFFFFFu, nq, off);
        na += __shfl_xor_sync(0xFFFFFFFFu, na, off);
        nc += __shfl_xor_sync(0xFFFFFFFFu, nc, off);
        qa += __shfl_xor_sync(0xFFFFFFFFu, qa, off);
        ac += __shfl_xor_sync(0xFFFFFFFFu, ac, off);
        qc += __shfl_xor_sync(0xFFFFFFFFu, qc, off);
    }

    __shared__ float s_loss[4];
    if (lid == 0) {
        float iq = 1.0f / fmaxf(sqrtf(nq), 1e-12f);
        float ia = 1.0f / fmaxf(sqrtf(na), 1e-12f);
        float ic = 1.0f / fmaxf(sqrtf(nc), 1e-12f);

        float dqa = qa * iq * ia;
        float dac = ac * ia * ic;
        float dqc = qc * iq * ic;

        float t0 = (float)t0i;
        float t1 = (float)t1i;

        float eqa = __expf(dqa);
        float eac = __expf(dac);
        float eqc = __expf(dqc);

        float up   = fmaxf((1.0f - t0) * eqa + (1.0f - t1) * eqc, 1e-8f);
        float down = fmaxf(t0 * eqa + t1 * eqc, 1e-8f);

        s_loss[wid] = __logf(up + eac) - __logf(down);

        int correct = (dqa > dqc) ? 1 : 0;
        float eq = (correct == t0i) ? 1.0f : 0.0f;
        if (1 + b < out_size) out[1 + b] = eq;
    }
    __syncthreads();

    // ---- Last-CTA reduction for the mean ----
    __shared__ bool s_last;
    if (t == 0) {
        g_partials[blockIdx.x] = s_loss[0] + s_loss[1] + s_loss[2] + s_loss[3];
        __threadfence();
        unsigned int ticket = atomicAdd(&g_count, 1u);
        s_last = (ticket == GRID - 1);
    }
    __syncthreads();

    if (s_last) {
        __threadfence();   // acquire: see all partials
        float sum = 0.f;
        #pragma unroll
        for (int i = 0; i < GRID / THREADS; i++)   // 8 per thread
            sum += g_partials[t + i * THREADS];

        // block reduce (128 threads)
        #pragma unroll
        for (int off = 16; off > 0; off >>= 1)
            sum += __shfl_xor_sync(0xFFFFFFFFu, sum, off);
        __shared__ float s_red[4];
        if (lid == 0) s_red[wid] = sum;
        __syncthreads();
        if (t == 0) {
            float total = s_red[0] + s_red[1] + s_red[2] + s_red[3];
            out[0] = total * (1.0f / (float)NB);
            g_count = 0;   // reset for next graph replay (deterministic)
        }
    }
}

extern "C" void kernel_launch(void* const* d_in, const int* in_sizes, int n_in,
                              void* d_out, int out_size) {
    const float* x      = (const float*)d_in[0];
    const int*   target = (const int*)d_in[1];
    float*       out    = (float*)d_out;

    loss_kernel<<<GRID, THREADS>>>(x, target, out, out_size);
}